// round 1
// baseline (speedup 1.0000x reference)
#include <cuda_runtime.h>
#include <cuda_bf16.h>

#define DIM 4096
#define TOTAL 16384
#define WIDTH 4
#define STATE_LEN 3
#define NSLOTS 256
#define BATCH 8

// ---------------------------------------------------------------------------
// Main conv kernel: out[d, t] = sum_k w[d,k] * tap_k + residual * x[d,t]
// Fast path (>=99.8% of threads): all 4 taps come from x within the same
// segment -> two aligned float4 loads + one float4 store, pure streaming.
// Slow path: per-element segment lookup, pulling from conv_states / zero.
// ---------------------------------------------------------------------------
__global__ void __launch_bounds__(256) conv_main_kernel(
    const float* __restrict__ x,
    const float* __restrict__ weight,
    const float* __restrict__ cs,
    const int* __restrict__ qsl,
    const int* __restrict__ ci,
    const int* __restrict__ im,
    const int* __restrict__ pad,
    const int* __restrict__ resc,
    float* __restrict__ out)
{
    __shared__ int   s_qsl[BATCH + 1];
    __shared__ int   s_ci[BATCH];
    __shared__ int   s_im[BATCH];
    __shared__ int   s_pad;
    __shared__ float s_res;

    if (threadIdx.x < BATCH + 1) s_qsl[threadIdx.x] = qsl[threadIdx.x];
    if (threadIdx.x < BATCH) {
        s_ci[threadIdx.x] = ci[threadIdx.x];
        s_im[threadIdx.x] = im[threadIdx.x];
    }
    if (threadIdx.x == 0) {
        s_pad = pad[0];
        s_res = resc[0] ? 1.0f : 0.0f;
    }
    __syncthreads();

    const int d  = blockIdx.y;
    const int t0 = (blockIdx.x * blockDim.x + threadIdx.x) * 4;

    const float4 wv = *(const float4*)(weight + (size_t)d * WIDTH);
    const float w0 = wv.x, w1 = wv.y, w2 = wv.z;
    const float w3r = wv.w + s_res;

    const float* xr = x + (size_t)d * TOTAL;

    // segment of t0 (searchsorted-right - 1, clipped)
    int seg = 0;
#pragma unroll
    for (int i = 1; i < BATCH; i++) seg += (t0 >= s_qsl[i]);

    float4 o;
    if (t0 - s_qsl[seg] >= STATE_LEN && t0 + 3 < s_qsl[seg + 1]) {
        // fast path: t0 >= 3 inside segment -> t0 >= 4 (t0 multiple of 4)
        const float4 xc = *(const float4*)(xr + t0);
        const float4 xp = *(const float4*)(xr + t0 - 4);
        o.x = xc.x * w3r + w2 * xp.w + w1 * xp.z + w0 * xp.y;
        o.y = xc.y * w3r + w2 * xc.x + w1 * xp.w + w0 * xp.z;
        o.z = xc.z * w3r + w2 * xc.y + w1 * xc.x + w0 * xp.w;
        o.w = xc.w * w3r + w2 * xc.z + w1 * xc.y + w0 * xc.x;
    } else {
        const float wk[3] = {w2, w1, w0};  // wk[joff-1] = weight for tap at t-joff
        float res[4];
#pragma unroll
        for (int e = 0; e < 4; e++) {
            const int t = t0 + e;
            int sg = 0;
#pragma unroll
            for (int i = 1; i < BATCH; i++) sg += (t >= s_qsl[i]);
            const int  p        = t - s_qsl[sg];
            const int  raw      = s_ci[sg];
            const bool valid    = (raw != s_pad);
            const int  slot     = valid ? raw : 0;
            const bool use_init = valid && (s_im[sg] != 0);

            float acc = xr[t] * w3r;
#pragma unroll
            for (int joff = 1; joff < WIDTH; joff++) {
                float v;
                if (p >= joff) {
                    v = xr[t - joff];
                } else if (use_init) {
                    // state index = STATE_LEN - joff + p, in [0, STATE_LEN-1]
                    v = cs[((size_t)slot * DIM + d) * STATE_LEN +
                           (STATE_LEN - joff + p)];
                } else {
                    v = 0.0f;
                }
                acc += wk[joff - 1] * v;
            }
            res[e] = acc;
        }
        o = make_float4(res[0], res[1], res[2], res[3]);
    }
    *(float4*)(out + (size_t)d * TOTAL + t0) = o;
}

// ---------------------------------------------------------------------------
// Overwrite the BATCH written slots in the already-copied output states.
// Reads the ORIGINAL input conv_states (no hazard with the copy).
// ---------------------------------------------------------------------------
__global__ void __launch_bounds__(256) states_scatter_kernel(
    const float* __restrict__ x,
    const float* __restrict__ cs,
    const int* __restrict__ qsl,
    const int* __restrict__ ci,
    const int* __restrict__ im,
    const int* __restrict__ pad,
    float* __restrict__ out_states)
{
    const int idx = blockIdx.x * blockDim.x + threadIdx.x;
    const int total = BATCH * DIM * STATE_LEN;
    if (idx >= total) return;

    const int b   = idx / (DIM * STATE_LEN);
    const int rem = idx % (DIM * STATE_LEN);
    const int d   = rem / STATE_LEN;
    const int j   = rem % STATE_LEN;

    const int slot = ci[b];
    if (slot == pad[0]) return;

    const int start = qsl[b];
    const int end   = qsl[b + 1];
    const int L     = end - start;
    const int gx    = end + j - STATE_LEN;

    float v;
    if (gx >= start) {
        v = x[(size_t)d * TOTAL + gx];
    } else if (im[b] != 0) {
        int sidx = L + j;
        sidx = sidx < 0 ? 0 : (sidx > STATE_LEN - 1 ? STATE_LEN - 1 : sidx);
        v = cs[((size_t)slot * DIM + d) * STATE_LEN + sidx];
    } else {
        v = 0.0f;
    }
    out_states[((size_t)slot * DIM + d) * STATE_LEN + j] = v;
}

extern "C" void kernel_launch(void* const* d_in, const int* in_sizes, int n_in,
                              void* d_out, int out_size) {
    const float* x    = (const float*)d_in[0];   // (DIM, TOTAL)
    const float* w    = (const float*)d_in[1];   // (DIM, WIDTH)
    const float* cs   = (const float*)d_in[2];   // (NSLOTS, DIM, STATE_LEN)
    const int*   qsl  = (const int*)d_in[3];     // (BATCH+1,)
    const int*   ci   = (const int*)d_in[4];     // (BATCH,)
    const int*   im   = (const int*)d_in[5];     // (BATCH,)
    const int*   pad  = (const int*)d_in[6];     // scalar
    const int*   resc = (const int*)d_in[7];     // scalar

    float* out        = (float*)d_out;
    float* out_states = out + (size_t)DIM * TOTAL;

    // Main conv: grid (T / (4*256), DIM)
    dim3 grid(TOTAL / (4 * 256), DIM);
    conv_main_kernel<<<grid, 256>>>(x, w, cs, qsl, ci, im, pad, resc, out);

    // Full state copy (D2D, near-peak BW), then small scatter overwrite.
    cudaMemcpyAsync(out_states, cs,
                    (size_t)NSLOTS * DIM * STATE_LEN * sizeof(float),
                    cudaMemcpyDeviceToDevice, 0);

    const int nscatter = BATCH * DIM * STATE_LEN;
    states_scatter_kernel<<<(nscatter + 255) / 256, 256>>>(
        x, cs, qsl, ci, im, pad, out_states);
}

// round 2
// speedup vs baseline: 1.2727x; 1.2727x over previous
#include <cuda_runtime.h>
#include <cuda_bf16.h>

#define DIM 4096
#define TOTAL 16384
#define WIDTH 4
#define STATE_LEN 3
#define NSLOTS 256
#define BATCH 8

// Conv: 8 floats per thread.
#define ELEMS_PER_THREAD 8
#define TPB 256
#define XBLKS (TOTAL / (ELEMS_PER_THREAD * TPB))     // 8
#define CONV_BLOCKS (DIM * XBLKS)                    // 32768
#define STATE_FLOATS (NSLOTS * DIM * STATE_LEN)      // 3,145,728
#define STATE_BLOCKS (STATE_FLOATS / 4 / TPB)        // 3072

// ---------------------------------------------------------------------------
// One fused kernel:
//   blocks [0, CONV_BLOCKS)              : main causal conv (streaming)
//   blocks [CONV_BLOCKS, +STATE_BLOCKS)  : write final conv_states directly
//                                          (copy for untouched slots, new
//                                          state for the 8 written slots)
// ---------------------------------------------------------------------------
__global__ void __launch_bounds__(TPB) fused_conv_kernel(
    const float* __restrict__ x,
    const float* __restrict__ weight,
    const float* __restrict__ cs,
    const int* __restrict__ qsl,
    const int* __restrict__ ci,
    const int* __restrict__ im,
    const int* __restrict__ pad,
    const int* __restrict__ resc,
    float* __restrict__ out,
    float* __restrict__ out_states)
{
    __shared__ int   s_qsl[BATCH + 1];
    __shared__ int   s_ci[BATCH];
    __shared__ int   s_im[BATCH];
    __shared__ int   s_pad;
    __shared__ float s_res;

    if (threadIdx.x < BATCH + 1) s_qsl[threadIdx.x] = qsl[threadIdx.x];
    if (threadIdx.x < BATCH) {
        s_ci[threadIdx.x] = ci[threadIdx.x];
        s_im[threadIdx.x] = im[threadIdx.x];
    }
    if (threadIdx.x == 0) {
        s_pad = pad[0];
        s_res = resc[0] ? 1.0f : 0.0f;
    }
    __syncthreads();

    const int bid = blockIdx.x;

    if (bid < CONV_BLOCKS) {
        // ----------------- conv region -----------------
        const int d    = bid >> 3;            // bid / XBLKS
        const int xblk = bid & (XBLKS - 1);
        const int t0   = (xblk * TPB + threadIdx.x) * ELEMS_PER_THREAD;

        const float4 wv = *(const float4*)(weight + (size_t)d * WIDTH);
        const float w0 = wv.x, w1 = wv.y, w2 = wv.z;
        const float w3r = wv.w + s_res;

        const float* xr = x + (size_t)d * TOTAL;

        int seg = 0;
#pragma unroll
        for (int i = 1; i < BATCH; i++) seg += (t0 >= s_qsl[i]);

        float4 o0, o1;
        if (t0 - s_qsl[seg] >= STATE_LEN &&
            t0 + ELEMS_PER_THREAD - 1 < s_qsl[seg + 1]) {
            // fast path: all 8 outputs draw taps from x inside one segment
            const float4 xp = *(const float4*)(xr + t0 - 4);
            const float4 xa = *(const float4*)(xr + t0);
            const float4 xb = *(const float4*)(xr + t0 + 4);
            o0.x = xa.x * w3r + w2 * xp.w + w1 * xp.z + w0 * xp.y;
            o0.y = xa.y * w3r + w2 * xa.x + w1 * xp.w + w0 * xp.z;
            o0.z = xa.z * w3r + w2 * xa.y + w1 * xa.x + w0 * xp.w;
            o0.w = xa.w * w3r + w2 * xa.z + w1 * xa.y + w0 * xa.x;
            o1.x = xb.x * w3r + w2 * xa.w + w1 * xa.z + w0 * xa.y;
            o1.y = xb.y * w3r + w2 * xb.x + w1 * xa.w + w0 * xa.z;
            o1.z = xb.z * w3r + w2 * xb.y + w1 * xb.x + w0 * xa.w;
            o1.w = xb.w * w3r + w2 * xb.z + w1 * xb.y + w0 * xb.x;
        } else {
            // slow path: per-element (segment boundaries only)
            const float wk[3] = {w2, w1, w0};
            float res[ELEMS_PER_THREAD];
#pragma unroll
            for (int e = 0; e < ELEMS_PER_THREAD; e++) {
                const int t = t0 + e;
                int sg = 0;
#pragma unroll
                for (int i = 1; i < BATCH; i++) sg += (t >= s_qsl[i]);
                const int  p        = t - s_qsl[sg];
                const int  raw      = s_ci[sg];
                const bool valid    = (raw != s_pad);
                const int  slot     = valid ? raw : 0;
                const bool use_init = valid && (s_im[sg] != 0);

                float acc = xr[t] * w3r;
#pragma unroll
                for (int joff = 1; joff < WIDTH; joff++) {
                    float v;
                    if (p >= joff) {
                        v = xr[t - joff];
                    } else if (use_init) {
                        v = cs[((size_t)slot * DIM + d) * STATE_LEN +
                               (STATE_LEN - joff + p)];
                    } else {
                        v = 0.0f;
                    }
                    acc += wk[joff - 1] * v;
                }
                res[e] = acc;
            }
            o0 = make_float4(res[0], res[1], res[2], res[3]);
            o1 = make_float4(res[4], res[5], res[6], res[7]);
        }
        float* op = out + (size_t)d * TOTAL + t0;
        __stcs((float4*)op, o0);
        __stcs((float4*)(op + 4), o1);
    } else {
        // ----------------- state region -----------------
        // Each thread owns one float4 of out_states (layout [slot][d][j],
        // slot chunk = DIM*3 floats, divisible by 4).
        const int sb  = bid - CONV_BLOCKS;
        const int f0  = (sb * TPB + threadIdx.x) * 4;   // linear float index
        const int slot = f0 / (DIM * STATE_LEN);

        // Is this slot one of the BATCH written slots?
        int wb = -1;
#pragma unroll
        for (int b = 0; b < BATCH; b++) {
            if (s_ci[b] == slot && s_ci[b] != s_pad) wb = b;
        }

        if (wb < 0) {
            // untouched slot: straight copy
            const float4 v = *(const float4*)(cs + f0);
            *(float4*)(out_states + f0) = v;
        } else {
            const int start = s_qsl[wb];
            const int end   = s_qsl[wb + 1];
            const int L     = end - start;
            const bool init = (s_im[wb] != 0);
            float r[4];
#pragma unroll
            for (int c = 0; c < 4; c++) {
                const int f  = f0 + c;
                const int rm = f - slot * (DIM * STATE_LEN);
                const int d  = rm / STATE_LEN;
                const int j  = rm - d * STATE_LEN;
                const int gx = end + j - STATE_LEN;
                float v;
                if (gx >= start) {
                    v = x[(size_t)d * TOTAL + gx];
                } else if (init) {
                    int sidx = L + j;
                    sidx = sidx < 0 ? 0 :
                           (sidx > STATE_LEN - 1 ? STATE_LEN - 1 : sidx);
                    v = cs[((size_t)slot * DIM + d) * STATE_LEN + sidx];
                } else {
                    v = 0.0f;
                }
                r[c] = v;
            }
            *(float4*)(out_states + f0) = make_float4(r[0], r[1], r[2], r[3]);
        }
    }
}

extern "C" void kernel_launch(void* const* d_in, const int* in_sizes, int n_in,
                              void* d_out, int out_size) {
    const float* x    = (const float*)d_in[0];   // (DIM, TOTAL)
    const float* w    = (const float*)d_in[1];   // (DIM, WIDTH)
    const float* cs   = (const float*)d_in[2];   // (NSLOTS, DIM, STATE_LEN)
    const int*   qsl  = (const int*)d_in[3];     // (BATCH+1,)
    const int*   ci   = (const int*)d_in[4];     // (BATCH,)
    const int*   im   = (const int*)d_in[5];     // (BATCH,)
    const int*   pad  = (const int*)d_in[6];     // scalar
    const int*   resc = (const int*)d_in[7];     // scalar

    float* out        = (float*)d_out;
    float* out_states = out + (size_t)DIM * TOTAL;

    fused_conv_kernel<<<CONV_BLOCKS + STATE_BLOCKS, TPB>>>(
        x, w, cs, qsl, ci, im, pad, resc, out, out_states);
}